// round 6
// baseline (speedup 1.0000x reference)
#include <cuda_runtime.h>
#include <math_constants.h>
#include <cstdint>

// Problem constants
#define BB 4
#define NP 16384           // original points per batch
#define CC 64              // input channels
#define NN 8192            // downsampled points per batch (8 frames * 1024)
#define KK 16              // knn k
#define OUTD 128           // out channels
#define PTS_TOTAL (BB*NN)             // 32768
#define ROWS_TOTAL (BB*NN*KK)         // 524288
#define NEIGH_BLOCKS 1024             // k_neigh grid (32 points per block)
#define KNN_CAP 24                    // pass-B per-query collect capacity

// Static scratch
__device__ float4 g_pos4[PTS_TOTAL];                  // (x,y,z,|p|^2)
__device__ float4 g_cand4[PTS_TOTAL];                 // (2x,2y,2z,-|p|^2)
__device__ int    g_knn[ROWS_TOTAL];                  // neighbor index sets (unordered)
__device__ float  g_y[(size_t)PTS_TOTAL * OUTD];      // per-point x@W0 + bias (16.8MB)
__device__ float  g_maxh[(size_t)PTS_TOTAL * OUTD];   // max over k of h (pre-BN)
__device__ float  g_minh[(size_t)PTS_TOTAL * OUTD];   // min over k of h (pre-BN)
__device__ float  g_partsum[NEIGH_BLOCKS * OUTD];
__device__ float  g_partsq [NEIGH_BLOCKS * OUTD];
__device__ float  g_scale[OUTD];
__device__ float  g_shift[OUTD];

// ---------------------------------------------------------------------------
// K0: temporal downsample -> pos4 / cand4, write new_pos output
// ---------------------------------------------------------------------------
__global__ void k_down(const float* __restrict__ pos, float* __restrict__ out_np, int write_np)
{
    int t = blockIdx.x * 256 + threadIdx.x;
    if (t >= PTS_TOTAL) return;
    int b = t >> 13;
    int n = t & (NN - 1);
    int orig = n + (n & ~1023);
    const float* p = pos + ((size_t)b * NP + orig) * 3;
    float x = p[0], y = p[1], z = p[2];
    float w = x*x + y*y + z*z;
    g_pos4[t]  = make_float4(x, y, z, w);
    g_cand4[t] = make_float4(2.f*x, 2.f*y, 2.f*z, -w);
    if (write_np) {
        float* o = out_np + (size_t)t * 3;
        o[0] = x; o[1] = y; o[2] = z;
    }
}

// ---------------------------------------------------------------------------
// K1: KNN, two-sweep per block (dynamic smem: tile + per-thread collect bufs).
//  Pass A: exact top-16 VALUES per query via compare-exchange insertion
//          (32 FMNMX, no indices), per-thread predicated branch (NO ballots —
//          with 32 distinct queries/warp a warp-uniform filter never prunes,
//          and VOTE latency dominated round-5's runtime).
//  Pass B: rescan; collect indices with pd >= thr (thr = exact 16th value);
//  Emit:   16 with exact top_k tie rule (>thr first, ==thr by scan order).
//  pd' = 2*dot(q,c) - |c|^2  (offset by -|q|^2 vs true pd: ordering identical)
// ---------------------------------------------------------------------------
__device__ __forceinline__ void ins16(float (&v)[16], float t)
{
    float x = t;
#pragma unroll
    for (int i = 0; i < 16; i++) {
        float lo = fminf(v[i], x);
        v[i] = fmaxf(v[i], x);
        x = lo;
    }
}

#define KNN_SMEM_BYTES (2048*16 + 128*KNN_CAP*8)   // 32KB tile + 24KB collect = 56KB

extern __shared__ unsigned char knn_smem_raw[];

__global__ void __launch_bounds__(128) k_knn2()
{
    float4* sh  = (float4*)knn_smem_raw;                       // [2048]
    float*  sBV = (float*)(knn_smem_raw + 2048 * 16);          // [128*KNN_CAP]
    int*    sBI = (int*)  (knn_smem_raw + 2048 * 16 + 128 * KNN_CAP * 4);

    int tid = threadIdx.x;
    int q   = blockIdx.x * 128 + tid;       // global query id
    int b   = q >> 13;
    float4 qp = g_pos4[q];
    float qx = qp.x, qy = qp.y, qz = qp.z;
    const float4* cand = g_cand4 + b * NN;

    float v[16];
#pragma unroll
    for (int i = 0; i < 16; i++) v[i] = -CUDART_INF_F;

    // ---- Pass A: top-16 values (predicated per-thread inserts) ----
    for (int t0 = 0; t0 < NN; t0 += 2048) {
        __syncthreads();
        for (int i = tid; i < 2048; i += 128)
            sh[i] = cand[t0 + i];
        __syncthreads();
#pragma unroll 4
        for (int j = 0; j < 2048; j += 2) {
            float4 c0 = sh[j];
            float4 c1 = sh[j + 1];
            float d0 = fmaf(c0.z, qz, fmaf(c0.y, qy, fmaf(c0.x, qx, c0.w)));
            float d1 = fmaf(c1.z, qz, fmaf(c1.y, qy, fmaf(c1.x, qx, c1.w)));
            if (d0 > v[15]) ins16(v, d0);
            if (d1 > v[15]) ins16(v, d1);
        }
    }
    float thr = v[15];

    // ---- Pass B: collect indices with pd >= thr ----
    int cur = 0;
    for (int t0 = 0; t0 < NN; t0 += 2048) {
        __syncthreads();
        for (int i = tid; i < 2048; i += 128)
            sh[i] = cand[t0 + i];
        __syncthreads();
#pragma unroll 4
        for (int j = 0; j < 2048; j += 2) {
            float4 c0 = sh[j];
            float4 c1 = sh[j + 1];
            float d0 = fmaf(c0.z, qz, fmaf(c0.y, qy, fmaf(c0.x, qx, c0.w)));
            float d1 = fmaf(c1.z, qz, fmaf(c1.y, qy, fmaf(c1.x, qx, c1.w)));
            if (d0 >= thr) {
                if (cur < KNN_CAP) { sBV[tid * KNN_CAP + cur] = d0; sBI[tid * KNN_CAP + cur] = t0 + j; }
                cur++;
            }
            if (d1 >= thr) {
                if (cur < KNN_CAP) { sBV[tid * KNN_CAP + cur] = d1; sBI[tid * KNN_CAP + cur] = t0 + j + 1; }
                cur++;
            }
        }
    }

    // ---- Emit exactly 16 with top_k tie rule ----
    int m = cur < KNN_CAP ? cur : KNN_CAP;
    int base = q * KK;
    int cnt = 0;
    for (int e = 0; e < m; e++) {
        if (sBV[tid * KNN_CAP + e] > thr && cnt < KK)
            g_knn[base + cnt++] = sBI[tid * KNN_CAP + e];
    }
    for (int e = 0; e < m; e++) {
        if (sBV[tid * KNN_CAP + e] == thr && cnt < KK)
            g_knn[base + cnt++] = sBI[tid * KNN_CAP + e];
    }
    // safety fill (unreachable in practice)
    while (cnt < KK) g_knn[base + cnt++] = q & (NN - 1);
}

// ---------------------------------------------------------------------------
// K2a: per-point GEMM  y[pt,:] = x[orig(pt),:] @ W[0:64,:] + bias
// 128 rows x 128 cols per block, 256 threads, 8x8 register tiles.
// ---------------------------------------------------------------------------
extern __shared__ float smem_g[];
__global__ void k_gemm_pt(const float* __restrict__ x,
                          const float* __restrict__ W,
                          const float* __restrict__ bias)
{
    float* sW = smem_g;              // [64*128]
    float* sF = smem_g + CC * OUTD;  // [64*128] x^T: sF[c*128+row]

    int tid = threadIdx.x;
    int r0  = blockIdx.x * 128;

    for (int i = tid; i < CC * OUTD; i += 256) sW[i] = W[i];

    {
        int l = tid >> 1, half = tid & 1;
        int r = r0 + l;
        int b = r >> 13;
        int n = r & (NN - 1);
        int orig = n + (n & ~1023);
        const float4* gx = (const float4*)(x + ((size_t)b * NP + orig) * CC);
#pragma unroll
        for (int i = 0; i < 8; i++) {
            float4 v = gx[half * 8 + i];
            int c0 = half * 32 + i * 4;
            sF[(c0 + 0) * 128 + l] = v.x;
            sF[(c0 + 1) * 128 + l] = v.y;
            sF[(c0 + 2) * 128 + l] = v.z;
            sF[(c0 + 3) * 128 + l] = v.w;
        }
    }
    __syncthreads();

    int tx = tid & 15, ty = tid >> 4;
    float acc[8][8];
#pragma unroll
    for (int c = 0; c < 8; c++) {
        float bv = bias[tx * 8 + c];
#pragma unroll
        for (int r = 0; r < 8; r++) acc[r][c] = bv;
    }

    for (int kk = 0; kk < CC; kk++) {
        float4 a0 = *(const float4*)&sF[kk * 128 + ty * 8];
        float4 a1 = *(const float4*)&sF[kk * 128 + ty * 8 + 4];
        float4 b0 = *(const float4*)&sW[kk * 128 + tx * 8];
        float4 b1 = *(const float4*)&sW[kk * 128 + tx * 8 + 4];
        float a[8]  = {a0.x, a0.y, a0.z, a0.w, a1.x, a1.y, a1.z, a1.w};
        float bb[8] = {b0.x, b0.y, b0.z, b0.w, b1.x, b1.y, b1.z, b1.w};
#pragma unroll
        for (int r = 0; r < 8; r++)
#pragma unroll
            for (int c = 0; c < 8; c++)
                acc[r][c] = fmaf(a[r], bb[c], acc[r][c]);
    }

#pragma unroll
    for (int r = 0; r < 8; r++) {
        float* dst = g_y + (size_t)(r0 + ty * 8 + r) * OUTD + tx * 8;
        ((float4*)dst)[0] = make_float4(acc[r][0], acc[r][1], acc[r][2], acc[r][3]);
        ((float4*)dst)[1] = make_float4(acc[r][4], acc[r][5], acc[r][6], acc[r][7]);
    }
}

// ---------------------------------------------------------------------------
// K2b: per (point, neighbor): h = y[idx] + posenc @ W[64:67]
//      fused max/min over K (pre-BN) + BN partial sums.
//      Block = 32 points, 256 threads (2 sub-groups x 128 channels).
// ---------------------------------------------------------------------------
__global__ void k_neigh(const float* __restrict__ W)
{
    __shared__ int   sIdx[512];
    __shared__ float sDx[512], sDy[512], sDz[512];
    __shared__ float red[256];

    int bi  = blockIdx.x;
    int p0  = bi * 32;                 // global point index (b*NN+n)
    int tid = threadIdx.x;

    for (int i = tid; i < 512; i += 256) {
        int pt  = p0 + (i >> 4);
        int k   = i & 15;
        int idx = g_knn[pt * KK + k];
        sIdx[i] = idx;
        int b = pt >> 13;
        float4 nb = g_pos4[b * NN + idx];
        float4 ct = g_pos4[pt];
        sDx[i] = nb.x - ct.x;
        sDy[i] = nb.y - ct.y;
        sDz[i] = nb.z - ct.z;
    }
    __syncthreads();

    int sub = tid >> 7, o = tid & 127;
    float w0 = W[64 * OUTD + o];
    float w1 = W[65 * OUTD + o];
    float w2 = W[66 * OUTD + o];
    int b = p0 >> 13;
    const float* yb = g_y + (size_t)b * NN * OUTD;

    float s = 0.f, q = 0.f;
    for (int i = 0; i < 16; i++) {
        int lp = sub * 16 + i;
        int pt = p0 + lp;
        float m  = -CUDART_INF_F;
        float mn =  CUDART_INF_F;
#pragma unroll
        for (int k = 0; k < KK; k++) {
            int e   = lp * KK + k;
            int idx = sIdx[e];
            float yv = yb[(size_t)idx * OUTD + o];
            float h = fmaf(sDx[e], w0, yv);
            h = fmaf(sDy[e], w1, h);
            h = fmaf(sDz[e], w2, h);
            m  = fmaxf(m, h);
            mn = fminf(mn, h);
            s += h;
            q  = fmaf(h, h, q);
        }
        g_maxh[(size_t)pt * OUTD + o] = m;
        g_minh[(size_t)pt * OUTD + o] = mn;
    }

    red[tid] = s; __syncthreads();
    if (sub == 0) g_partsum[bi * OUTD + o] = red[o] + red[128 + o];
    __syncthreads();
    red[tid] = q; __syncthreads();
    if (sub == 0) g_partsq[bi * OUTD + o] = red[o] + red[128 + o];
}

// ---------------------------------------------------------------------------
// K3: finalize BN stats -> per-channel scale/shift
// ---------------------------------------------------------------------------
__global__ void k_stats(const float* __restrict__ gamma, const float* __restrict__ beta)
{
    __shared__ double rs[256], rq[256];
    int col = blockIdx.x;
    double s = 0.0, q = 0.0;
    for (int i = threadIdx.x; i < NEIGH_BLOCKS; i += 256) {
        s += (double)g_partsum[i * OUTD + col];
        q += (double)g_partsq [i * OUTD + col];
    }
    rs[threadIdx.x] = s; rq[threadIdx.x] = q;
    __syncthreads();
    for (int st = 128; st > 0; st >>= 1) {
        if (threadIdx.x < st) {
            rs[threadIdx.x] += rs[threadIdx.x + st];
            rq[threadIdx.x] += rq[threadIdx.x + st];
        }
        __syncthreads();
    }
    if (threadIdx.x == 0) {
        double cnt = (double)ROWS_TOTAL;
        double mu  = rs[0] / cnt;
        double var = rq[0] / cnt - mu * mu;
        double rstd = 1.0 / sqrt(var + 1e-5);
        float sc = (float)rstd * gamma[col];
        float sh = beta[col] - (float)mu * sc;
        g_scale[col] = sc;
        g_shift[col] = sh;
    }
}

// ---------------------------------------------------------------------------
// K4: out[b,n,:] = relu(BN(extremum_k h[b,n,k,:])) + mean_k relu(BN(h[0,n,k,:]))
// batch-0 h recomputed on the fly from y (identical FMA order to k_neigh).
// ---------------------------------------------------------------------------
__global__ void k_out(const float* __restrict__ W, float* __restrict__ out)
{
    __shared__ int   sIdx[KK];
    __shared__ float sDx[KK], sDy[KK], sDz[KK];

    int n = blockIdx.x;
    int o = threadIdx.x;

    if (o < KK) {
        int idx = g_knn[n * KK + o];   // batch 0
        sIdx[o] = idx;
        float4 nb = g_pos4[idx];
        float4 ct = g_pos4[n];
        sDx[o] = nb.x - ct.x;
        sDy[o] = nb.y - ct.y;
        sDz[o] = nb.z - ct.z;
    }
    __syncthreads();

    float w0 = W[64 * OUTD + o];
    float w1 = W[65 * OUTD + o];
    float w2 = W[66 * OUTD + o];
    float sc = g_scale[o], sh = g_shift[o];

    float s = 0.f;
#pragma unroll
    for (int k = 0; k < KK; k++) {
        float yv = g_y[(size_t)sIdx[k] * OUTD + o];
        float h = fmaf(sDx[k], w0, yv);
        h = fmaf(sDy[k], w1, h);
        h = fmaf(sDz[k], w2, h);
        float v = fmaf(h, sc, sh);
        v = v > 0.f ? v : 0.f;
        s += v;
    }
    s *= (1.0f / KK);

    bool pos = (sc >= 0.f);
#pragma unroll
    for (int b = 0; b < BB; b++) {
        size_t off = (size_t)(b * NN + n) * OUTD + o;
        float hm = pos ? g_maxh[off] : g_minh[off];
        float v = fmaf(hm, sc, sh);
        v = v > 0.f ? v : 0.f;
        out[off] = v + s;
    }
}

// ---------------------------------------------------------------------------
extern "C" void kernel_launch(void* const* d_in, const int* in_sizes, int n_in,
                              void* d_out, int out_size)
{
    const float* x     = (const float*)d_in[0];
    const float* pos   = (const float*)d_in[1];
    const float* W     = (const float*)d_in[2];
    const float* bias  = (const float*)d_in[3];
    const float* gamma = (const float*)d_in[4];
    const float* beta  = (const float*)d_in[5];
    float* out = (float*)d_out;

    const int OUT_MAIN = PTS_TOTAL * OUTD;
    int write_np = (out_size >= OUT_MAIN + PTS_TOTAL * 3) ? 1 : 0;

    k_down<<<(PTS_TOTAL + 255) / 256, 256>>>(pos, out + OUT_MAIN, write_np);

    cudaFuncSetAttribute(k_knn2, cudaFuncAttributeMaxDynamicSharedMemorySize, KNN_SMEM_BYTES);
    k_knn2<<<PTS_TOTAL / 128, 128, KNN_SMEM_BYTES>>>();

    int smem_bytes = 2 * CC * OUTD * (int)sizeof(float);   // 65536
    cudaFuncSetAttribute(k_gemm_pt, cudaFuncAttributeMaxDynamicSharedMemorySize, smem_bytes);
    k_gemm_pt<<<PTS_TOTAL / 128, 256, smem_bytes>>>(x, W, bias);

    k_neigh<<<NEIGH_BLOCKS, 256>>>(W);

    k_stats<<<OUTD, 256>>>(gamma, beta);

    k_out<<<NN, 128>>>(W, out);
}

// round 7
// speedup vs baseline: 1.3992x; 1.3992x over previous
#include <cuda_runtime.h>
#include <math_constants.h>
#include <cstdint>

// Problem constants
#define BB 4
#define NP 16384           // original points per batch
#define CC 64              // input channels
#define NN 8192            // downsampled points per batch (8 frames * 1024)
#define KK 16              // knn k
#define OUTD 128           // out channels
#define PTS_TOTAL (BB*NN)             // 32768
#define ROWS_TOTAL (BB*NN*KK)         // 524288
#define NEIGH_BLOCKS 1024             // k_neigh grid (32 points per block)
#define KNN_SPLIT 2
#define ACC_CAP 160                   // per-thread accept-log capacity (mean 105, 6.5 sigma)

// Static scratch
__device__ float4 g_pos4[PTS_TOTAL];                  // (x,y,z,|p|^2)
__device__ float4 g_cand4[PTS_TOTAL];                 // (2x,2y,2z,-|p|^2)
__device__ float  g_kv[PTS_TOTAL * KNN_SPLIT * KK];   // per-half top-k vals (sorted desc)
__device__ int    g_ki[PTS_TOTAL * KNN_SPLIT * KK];   // per-half top-k idx (batch-local)
__device__ int    g_knn[ROWS_TOTAL];                  // merged neighbor indices
__device__ float  g_y[(size_t)PTS_TOTAL * OUTD];      // per-point x@W0 + bias (16.8MB)
__device__ float  g_maxh[(size_t)PTS_TOTAL * OUTD];   // max over k of h (pre-BN)
__device__ float  g_minh[(size_t)PTS_TOTAL * OUTD];   // min over k of h (pre-BN)
__device__ float  g_partsum[NEIGH_BLOCKS * OUTD];
__device__ float  g_partsq [NEIGH_BLOCKS * OUTD];
__device__ float  g_scale[OUTD];
__device__ float  g_shift[OUTD];

// ---------------------------------------------------------------------------
// K0: temporal downsample -> pos4 / cand4, write new_pos output
// ---------------------------------------------------------------------------
__global__ void k_down(const float* __restrict__ pos, float* __restrict__ out_np, int write_np)
{
    int t = blockIdx.x * 256 + threadIdx.x;
    if (t >= PTS_TOTAL) return;
    int b = t >> 13;
    int n = t & (NN - 1);
    int orig = n + (n & ~1023);
    const float* p = pos + ((size_t)b * NP + orig) * 3;
    float x = p[0], y = p[1], z = p[2];
    float w = x*x + y*y + z*z;
    g_pos4[t]  = make_float4(x, y, z, w);
    g_cand4[t] = make_float4(2.f*x, 2.f*y, 2.f*z, -w);
    if (write_np) {
        float* o = out_np + (size_t)t * 3;
        o[0] = x; o[1] = y; o[2] = z;
    }
}

// ---------------------------------------------------------------------------
// K1: KNN with values-only top-16 (32 FMNMX compare-exchange insertion) plus
//     a per-thread local-memory ACCEPT LOG — every candidate that beats the
//     running 16th value is appended. The final top-16 set is recovered from
//     the log by filtering against thr = final 16th value with the exact
//     top_k tie rule (> thr, then == thr in scan/index order). One scan,
//     no index tracking in the hot insert, no rescan pass.
//     split 2: each thread handles one (query, candidate-half).
//  pd' = 2*dot(q,c) - |c|^2  (offset by -|q|^2 vs true pd: ordering identical)
// ---------------------------------------------------------------------------
__device__ __forceinline__ void ins16(float (&v)[16], float t)
{
    float x = t;
#pragma unroll
    for (int i = 0; i < 16; i++) {
        float lo = fminf(v[i], x);
        v[i] = fmaxf(v[i], x);
        x = lo;
    }
}

__global__ void __launch_bounds__(256) k_knn3()
{
    __shared__ float4 sh[2048];

    int tid = threadIdx.x;
    int b = blockIdx.y;
    int z = blockIdx.z;
    int n = blockIdx.x * 256 + tid;
    float4 qp = g_pos4[b * NN + n];
    float qx = qp.x, qy = qp.y, qz = qp.z;
    int zofs = z * (NN / KNN_SPLIT);
    const float4* cand = g_cand4 + b * NN + zofs;

    float v[16];
#pragma unroll
    for (int i = 0; i < 16; i++) v[i] = -CUDART_INF_F;

    float lv[ACC_CAP];   // local-memory accept log (values)
    int   li[ACC_CAP];   // local-memory accept log (batch-local indices)
    int   cur = 0;

    for (int t0 = 0; t0 < NN / KNN_SPLIT; t0 += 2048) {
        __syncthreads();
        for (int i = tid; i < 2048; i += 256)
            sh[i] = cand[t0 + i];
        __syncthreads();
#pragma unroll 4
        for (int j = 0; j < 2048; j += 2) {
            float4 c0 = sh[j];
            float4 c1 = sh[j + 1];
            float d0 = fmaf(c0.z, qz, fmaf(c0.y, qy, fmaf(c0.x, qx, c0.w)));
            float d1 = fmaf(c1.z, qz, fmaf(c1.y, qy, fmaf(c1.x, qx, c1.w)));
            if (d0 > v[15]) {
                ins16(v, d0);
                if (cur < ACC_CAP) { lv[cur] = d0; li[cur] = zofs + t0 + j; }
                cur++;
            }
            if (d1 > v[15]) {
                ins16(v, d1);
                if (cur < ACC_CAP) { lv[cur] = d1; li[cur] = zofs + t0 + j + 1; }
                cur++;
            }
        }
    }

    // ---- Recover exact top-16 (val, idx) from the accept log ----
    float thr = v[15];
    int m = cur < ACC_CAP ? cur : ACC_CAP;

    float fv[16]; int fi[16];
    int cnt = 0;
    for (int e = 0; e < m; e++) {
        float val = lv[e];
        if (val > thr && cnt < KK) { fv[cnt] = val; fi[cnt] = li[e]; cnt++; }
    }
    for (int e = 0; e < m; e++) {
        float val = lv[e];
        if (val == thr && cnt < KK) { fv[cnt] = val; fi[cnt] = li[e]; cnt++; }
    }
    while (cnt < KK) { fv[cnt] = -CUDART_INF_F; fi[cnt] = n; cnt++; }

    // ---- Sort the 16 pairs desc by value (stable: earlier = higher rank) ----
    float sv[16]; int si[16];
#pragma unroll
    for (int i = 0; i < 16; i++) { sv[i] = -CUDART_INF_F; si[i] = n; }
#pragma unroll
    for (int e = 0; e < 16; e++) {
        float val = fv[e];
        if (val > sv[15]) {
            sv[15] = val; si[15] = fi[e];
#pragma unroll
            for (int s = 15; s > 0; --s) {
                if (sv[s] > sv[s-1]) {
                    float tv = sv[s]; sv[s] = sv[s-1]; sv[s-1] = tv;
                    int   ti = si[s]; si[s] = si[s-1]; si[s-1] = ti;
                }
            }
        }
    }

    int base = ((b * NN + n) * KNN_SPLIT + z) * KK;
#pragma unroll
    for (int i = 0; i < 16; i++) { g_kv[base + i] = sv[i]; g_ki[base + i] = si[i]; }
}

// ---------------------------------------------------------------------------
// K1b: merge the two sorted 16-lists per query (ties -> half 0 = lower index)
// ---------------------------------------------------------------------------
__global__ void k_merge()
{
    int t = blockIdx.x * 256 + threadIdx.x;
    if (t >= PTS_TOTAL) return;
    const float* v  = g_kv + (size_t)t * (KNN_SPLIT * KK);
    const int*   id = g_ki + (size_t)t * (KNN_SPLIT * KK);
    int i = 0, j = KK;
    int base = t * KK;
#pragma unroll
    for (int o = 0; o < KK; o++) {
        float a  = (i < KK)      ? v[i] : -CUDART_INF_F;
        float bq = (j < 2 * KK)  ? v[j] : -CUDART_INF_F;
        bool ta = (a >= bq);
        g_knn[base + o] = ta ? id[i] : id[j];
        i += ta ? 1 : 0;
        j += ta ? 0 : 1;
    }
}

// ---------------------------------------------------------------------------
// K2a: per-point GEMM  y[pt,:] = x[orig(pt),:] @ W[0:64,:] + bias
// 128 rows x 128 cols per block, 256 threads, 8x8 register tiles.
// ---------------------------------------------------------------------------
extern __shared__ float smem_g[];
__global__ void k_gemm_pt(const float* __restrict__ x,
                          const float* __restrict__ W,
                          const float* __restrict__ bias)
{
    float* sW = smem_g;              // [64*128]
    float* sF = smem_g + CC * OUTD;  // [64*128] x^T: sF[c*128+row]

    int tid = threadIdx.x;
    int r0  = blockIdx.x * 128;

    for (int i = tid; i < CC * OUTD; i += 256) sW[i] = W[i];

    {
        int l = tid >> 1, half = tid & 1;
        int r = r0 + l;
        int b = r >> 13;
        int n = r & (NN - 1);
        int orig = n + (n & ~1023);
        const float4* gx = (const float4*)(x + ((size_t)b * NP + orig) * CC);
#pragma unroll
        for (int i = 0; i < 8; i++) {
            float4 v = gx[half * 8 + i];
            int c0 = half * 32 + i * 4;
            sF[(c0 + 0) * 128 + l] = v.x;
            sF[(c0 + 1) * 128 + l] = v.y;
            sF[(c0 + 2) * 128 + l] = v.z;
            sF[(c0 + 3) * 128 + l] = v.w;
        }
    }
    __syncthreads();

    int tx = tid & 15, ty = tid >> 4;
    float acc[8][8];
#pragma unroll
    for (int c = 0; c < 8; c++) {
        float bv = bias[tx * 8 + c];
#pragma unroll
        for (int r = 0; r < 8; r++) acc[r][c] = bv;
    }

    for (int kk = 0; kk < CC; kk++) {
        float4 a0 = *(const float4*)&sF[kk * 128 + ty * 8];
        float4 a1 = *(const float4*)&sF[kk * 128 + ty * 8 + 4];
        float4 b0 = *(const float4*)&sW[kk * 128 + tx * 8];
        float4 b1 = *(const float4*)&sW[kk * 128 + tx * 8 + 4];
        float a[8]  = {a0.x, a0.y, a0.z, a0.w, a1.x, a1.y, a1.z, a1.w};
        float bb[8] = {b0.x, b0.y, b0.z, b0.w, b1.x, b1.y, b1.z, b1.w};
#pragma unroll
        for (int r = 0; r < 8; r++)
#pragma unroll
            for (int c = 0; c < 8; c++)
                acc[r][c] = fmaf(a[r], bb[c], acc[r][c]);
    }

#pragma unroll
    for (int r = 0; r < 8; r++) {
        float* dst = g_y + (size_t)(r0 + ty * 8 + r) * OUTD + tx * 8;
        ((float4*)dst)[0] = make_float4(acc[r][0], acc[r][1], acc[r][2], acc[r][3]);
        ((float4*)dst)[1] = make_float4(acc[r][4], acc[r][5], acc[r][6], acc[r][7]);
    }
}

// ---------------------------------------------------------------------------
// K2b: per (point, neighbor): h = y[idx] + posenc @ W[64:67]
//      fused max/min over K (pre-BN) + BN partial sums.
//      Block = 32 points, 256 threads (2 sub-groups x 128 channels).
// ---------------------------------------------------------------------------
__global__ void k_neigh(const float* __restrict__ W)
{
    __shared__ int   sIdx[512];
    __shared__ float sDx[512], sDy[512], sDz[512];
    __shared__ float red[256];

    int bi  = blockIdx.x;
    int p0  = bi * 32;                 // global point index (b*NN+n)
    int tid = threadIdx.x;

    for (int i = tid; i < 512; i += 256) {
        int pt  = p0 + (i >> 4);
        int k   = i & 15;
        int idx = g_knn[pt * KK + k];
        sIdx[i] = idx;
        int b = pt >> 13;
        float4 nb = g_pos4[b * NN + idx];
        float4 ct = g_pos4[pt];
        sDx[i] = nb.x - ct.x;
        sDy[i] = nb.y - ct.y;
        sDz[i] = nb.z - ct.z;
    }
    __syncthreads();

    int sub = tid >> 7, o = tid & 127;
    float w0 = W[64 * OUTD + o];
    float w1 = W[65 * OUTD + o];
    float w2 = W[66 * OUTD + o];
    int b = p0 >> 13;
    const float* yb = g_y + (size_t)b * NN * OUTD;

    float s = 0.f, q = 0.f;
    for (int i = 0; i < 16; i++) {
        int lp = sub * 16 + i;
        int pt = p0 + lp;
        float m  = -CUDART_INF_F;
        float mn =  CUDART_INF_F;
#pragma unroll
        for (int k = 0; k < KK; k++) {
            int e   = lp * KK + k;
            int idx = sIdx[e];
            float yv = yb[(size_t)idx * OUTD + o];
            float h = fmaf(sDx[e], w0, yv);
            h = fmaf(sDy[e], w1, h);
            h = fmaf(sDz[e], w2, h);
            m  = fmaxf(m, h);
            mn = fminf(mn, h);
            s += h;
            q  = fmaf(h, h, q);
        }
        g_maxh[(size_t)pt * OUTD + o] = m;
        g_minh[(size_t)pt * OUTD + o] = mn;
    }

    red[tid] = s; __syncthreads();
    if (sub == 0) g_partsum[bi * OUTD + o] = red[o] + red[128 + o];
    __syncthreads();
    red[tid] = q; __syncthreads();
    if (sub == 0) g_partsq[bi * OUTD + o] = red[o] + red[128 + o];
}

// ---------------------------------------------------------------------------
// K3: finalize BN stats -> per-channel scale/shift
// ---------------------------------------------------------------------------
__global__ void k_stats(const float* __restrict__ gamma, const float* __restrict__ beta)
{
    __shared__ double rs[256], rq[256];
    int col = blockIdx.x;
    double s = 0.0, q = 0.0;
    for (int i = threadIdx.x; i < NEIGH_BLOCKS; i += 256) {
        s += (double)g_partsum[i * OUTD + col];
        q += (double)g_partsq [i * OUTD + col];
    }
    rs[threadIdx.x] = s; rq[threadIdx.x] = q;
    __syncthreads();
    for (int st = 128; st > 0; st >>= 1) {
        if (threadIdx.x < st) {
            rs[threadIdx.x] += rs[threadIdx.x + st];
            rq[threadIdx.x] += rq[threadIdx.x + st];
        }
        __syncthreads();
    }
    if (threadIdx.x == 0) {
        double cnt = (double)ROWS_TOTAL;
        double mu  = rs[0] / cnt;
        double var = rq[0] / cnt - mu * mu;
        double rstd = 1.0 / sqrt(var + 1e-5);
        float sc = (float)rstd * gamma[col];
        float sh = beta[col] - (float)mu * sc;
        g_scale[col] = sc;
        g_shift[col] = sh;
    }
}

// ---------------------------------------------------------------------------
// K4: out[b,n,:] = relu(BN(extremum_k h[b,n,k,:])) + mean_k relu(BN(h[0,n,k,:]))
// batch-0 h recomputed on the fly from y (identical FMA order to k_neigh).
// ---------------------------------------------------------------------------
__global__ void k_out(const float* __restrict__ W, float* __restrict__ out)
{
    __shared__ int   sIdx[KK];
    __shared__ float sDx[KK], sDy[KK], sDz[KK];

    int n = blockIdx.x;
    int o = threadIdx.x;

    if (o < KK) {
        int idx = g_knn[n * KK + o];   // batch 0
        sIdx[o] = idx;
        float4 nb = g_pos4[idx];
        float4 ct = g_pos4[n];
        sDx[o] = nb.x - ct.x;
        sDy[o] = nb.y - ct.y;
        sDz[o] = nb.z - ct.z;
    }
    __syncthreads();

    float w0 = W[64 * OUTD + o];
    float w1 = W[65 * OUTD + o];
    float w2 = W[66 * OUTD + o];
    float sc = g_scale[o], sh = g_shift[o];

    float s = 0.f;
#pragma unroll
    for (int k = 0; k < KK; k++) {
        float yv = g_y[(size_t)sIdx[k] * OUTD + o];
        float h = fmaf(sDx[k], w0, yv);
        h = fmaf(sDy[k], w1, h);
        h = fmaf(sDz[k], w2, h);
        float v = fmaf(h, sc, sh);
        v = v > 0.f ? v : 0.f;
        s += v;
    }
    s *= (1.0f / KK);

    bool pos = (sc >= 0.f);
#pragma unroll
    for (int b = 0; b < BB; b++) {
        size_t off = (size_t)(b * NN + n) * OUTD + o;
        float hm = pos ? g_maxh[off] : g_minh[off];
        float v = fmaf(hm, sc, sh);
        v = v > 0.f ? v : 0.f;
        out[off] = v + s;
    }
}

// ---------------------------------------------------------------------------
extern "C" void kernel_launch(void* const* d_in, const int* in_sizes, int n_in,
                              void* d_out, int out_size)
{
    const float* x     = (const float*)d_in[0];
    const float* pos   = (const float*)d_in[1];
    const float* W     = (const float*)d_in[2];
    const float* bias  = (const float*)d_in[3];
    const float* gamma = (const float*)d_in[4];
    const float* beta  = (const float*)d_in[5];
    float* out = (float*)d_out;

    const int OUT_MAIN = PTS_TOTAL * OUTD;
    int write_np = (out_size >= OUT_MAIN + PTS_TOTAL * 3) ? 1 : 0;

    k_down<<<(PTS_TOTAL + 255) / 256, 256>>>(pos, out + OUT_MAIN, write_np);

    dim3 gk(NN / 256, BB, KNN_SPLIT);
    k_knn3<<<gk, 256>>>();

    k_merge<<<PTS_TOTAL / 256, 256>>>();

    int smem_bytes = 2 * CC * OUTD * (int)sizeof(float);   // 65536
    cudaFuncSetAttribute(k_gemm_pt, cudaFuncAttributeMaxDynamicSharedMemorySize, smem_bytes);
    k_gemm_pt<<<PTS_TOTAL / 128, 256, smem_bytes>>>(x, W, bias);

    k_neigh<<<NEIGH_BLOCKS, 256>>>(W);

    k_stats<<<OUTD, 256>>>(gamma, beta);

    k_out<<<NN, 128>>>(W, out);
}